// round 5
// baseline (speedup 1.0000x reference)
#include <cuda_runtime.h>
#include <math.h>

#define BATCH 2
#define NPTS  8192
#define IC    64
#define OC    128
#define KNN   16
#define NROWS (BATCH*NPTS)      /* 16384 */
#define EPSF  1e-5f

#define GSEG  8                 /* KNN candidate segments per query */
#define SEGN  (NPTS/GSEG)       /* 1024 */
#define BCAP  40
#define BTRIG 32
#define K2_GRID 148

typedef unsigned long long ull;

/* ---------------- scratch (no allocations allowed) ---------------- */
__device__ int   g_knn[NROWS*KNN];
__device__ float g_ypre[NROWS*OC];
__device__ float g_segd[GSEG*KNN*NROWS];
__device__ int   g_segi[GSEG*KNN*NROWS];
__device__ float g_part[K2_GRID*OC*2];

__device__ __forceinline__ float gelu_f(float x){
    return 0.5f*x*(1.0f + erff(x*0.70710678118654752440f));
}

/* ---------------- packed f32x2 helpers ---------------- */
__device__ __forceinline__ ull pk(float lo, float hi){
    ull r; asm("mov.b64 %0,{%1,%2};" : "=l"(r) : "f"(lo), "f"(hi)); return r;
}
__device__ __forceinline__ void upk(ull v, float& lo, float& hi){
    asm("mov.b64 {%0,%1},%2;" : "=f"(lo), "=f"(hi) : "l"(v));
}
__device__ __forceinline__ ull mul2(ull a, ull b){
    ull r; asm("mul.rn.f32x2 %0,%1,%2;" : "=l"(r) : "l"(a), "l"(b)); return r;
}
__device__ __forceinline__ ull add2(ull a, ull b){
    ull r; asm("add.rn.f32x2 %0,%1,%2;" : "=l"(r) : "l"(a), "l"(b)); return r;
}
__device__ __forceinline__ ull fma2(ull a, ull b, ull c){
    ull r; asm("fma.rn.f32x2 %0,%1,%2,%3;" : "=l"(r) : "l"(a), "l"(b), "l"(c)); return r;
}
__device__ __forceinline__ ull lds64(unsigned a){
    ull v; asm volatile("ld.shared.b64 %0,[%1];" : "=l"(v) : "r"(a)); return v;
}
__device__ __forceinline__ void lds128p(unsigned a, ull& x01, ull& x23){
    asm volatile("ld.shared.v2.b64 {%0,%1},[%2];" : "=l"(x01), "=l"(x23) : "r"(a));
}

/* =============== K1a: segmented KNN, SoA tile + packed distances =============== */
#define K1_THREADS 128
#define TILE_C     SEGN

#define FLUSH() do{                                                   \
    for (int t = 0; t < cnt; t++){                                    \
        float d2f = bd[t]; int jj = bi[t];                            \
        _Pragma("unroll")                                             \
        for (int s = 0; s < KNN; s++){                                \
            bool  lt = d2f < kd[s];                                   \
            float od = kd[s]; int oi = ki[s];                         \
            kd[s] = lt ? d2f : od;  ki[s] = lt ? jj : oi;             \
            d2f   = lt ? od  : d2f; jj    = lt ? oi : jj;             \
        }                                                             \
    }                                                                 \
    cnt = 0; kmax = kd[KNN-1];                                        \
}while(0)

__global__ void __launch_bounds__(K1_THREADS)
knn_seg_kernel(const float* __restrict__ pts)
{
    __shared__ __align__(16) float sXx[TILE_C];
    __shared__ __align__(16) float sYy[TILE_C];
    __shared__ __align__(16) float sZz[TILE_C];
    __shared__ __align__(16) float sWw[TILE_C];

    const int q     = blockIdx.x * K1_THREADS + threadIdx.x;
    const int seg   = blockIdx.y;
    const int cbase = (q >> 13) << 13;
    const int sbase = cbase + seg*SEGN;

    const float qx = pts[q*3+0], qy = pts[q*3+1], qz = pts[q*3+2];
    const float qs = qx*qx + qy*qy + qz*qz;

    for (int t = threadIdx.x; t < TILE_C; t += K1_THREADS){
        const int j = sbase + t;
        float x = pts[j*3+0], y = pts[j*3+1], z = pts[j*3+2];
        sXx[t] = x; sYy[t] = y; sZz[t] = z;
        sWw[t] = x*x + y*y + z*z;
    }
    __syncthreads();

    const unsigned aX = (unsigned)__cvta_generic_to_shared(sXx);
    const unsigned aY = (unsigned)__cvta_generic_to_shared(sYy);
    const unsigned aZ = (unsigned)__cvta_generic_to_shared(sZz);
    const unsigned aW = (unsigned)__cvta_generic_to_shared(sWw);

    const ull qx2 = pk(qx,qx), qy2 = pk(qy,qy), qz2 = pk(qz,qz);
    const ull qs2 = pk(qs,qs), m2  = pk(-2.0f,-2.0f);

    float kd[KNN]; int ki[KNN];
#pragma unroll
    for (int s = 0; s < KNN; s++){ kd[s] = 3.4e38f; ki[s] = cbase; }
    float bd[BCAP]; int bi[BCAP];
    int   cnt = 0;
    float kmax = 3.4e38f;

#pragma unroll 2
    for (int p = 0; p < TILE_C/2; p++){
        const ull cx = lds64(aX + p*8);
        const ull cy = lds64(aY + p*8);
        const ull cz = lds64(aZ + p*8);
        const ull cw = lds64(aW + p*8);
        /* same per-element op order as scalar version: mul, fma, fma */
        ull dot  = fma2(qz2, cz, fma2(qy2, cy, mul2(qx2, cx)));
        ull base = add2(qs2, cw);
        ull d2p  = fma2(m2, dot, base);
        float d0, d1; upk(d2p, d0, d1);
        if (d0 < kmax){ bd[cnt] = d0; bi[cnt] = sbase + 2*p;     cnt++; }
        if (d1 < kmax){ bd[cnt] = d1; bi[cnt] = sbase + 2*p + 1; cnt++; }
        if (p & 1){
            if (__any_sync(0xffffffffu, cnt >= BTRIG)) FLUSH();
        }
    }
    FLUSH();

#pragma unroll
    for (int t = 0; t < KNN; t++){
        g_segd[(seg*KNN + t)*NROWS + q] = kd[t];
        g_segi[(seg*KNN + t)*NROWS + q] = ki[t];
    }
}

/* =============== K1b: bitonic top-16 merge tree (register-only) =============== */
__device__ __forceinline__ bool lexlt(float d1, int i1, float d2, int i2){
    return (d1 < d2) || (d1 == d2 && i1 < i2);
}

__device__ __forceinline__ void mergeTop16(float* ad, int* ai,
                                           const float* bdv, const int* biv)
{
    float td[16]; int ti[16];
#pragma unroll
    for (int i = 0; i < 16; i++){
        float db = bdv[15-i]; int ib = biv[15-i];
        bool t = lexlt(db, ib, ad[i], ai[i]);
        td[i] = t ? db : ad[i];
        ti[i] = t ? ib : ai[i];
    }
#pragma unroll
    for (int k = 8; k >= 1; k >>= 1){
#pragma unroll
        for (int i = 0; i < 16; i++){
            if ((i & k) == 0){
                const int j = i + k;
                bool sw = lexlt(td[j], ti[j], td[i], ti[i]);
                float d0 = td[i]; int i0 = ti[i];
                td[i] = sw ? td[j] : d0;   ti[i] = sw ? ti[j] : i0;
                td[j] = sw ? d0 : td[j];   ti[j] = sw ? i0 : ti[j];
            }
        }
    }
#pragma unroll
    for (int i = 0; i < 16; i++){ ad[i] = td[i]; ai[i] = ti[i]; }
}

#define LOADSEG(s, D, I) do{                                  \
    _Pragma("unroll")                                         \
    for (int t = 0; t < 16; t++){                             \
        D[t] = g_segd[((s)*KNN + t)*NROWS + q];               \
        I[t] = g_segi[((s)*KNN + t)*NROWS + q];               \
    }                                                         \
}while(0)

__global__ void __launch_bounds__(256)
knn_merge_kernel(void)
{
    const int q = blockIdx.x*256 + threadIdx.x;
    float A[16], B[16], C[16], D[16];
    int   Ai[16], Bi[16], Ci[16], Di[16];

    LOADSEG(0, A, Ai); LOADSEG(1, B, Bi);
    mergeTop16(A, Ai, B, Bi);                 /* A = top(0,1) */
    LOADSEG(2, B, Bi); LOADSEG(3, C, Ci);
    mergeTop16(B, Bi, C, Ci);                 /* B = top(2,3) */
    mergeTop16(A, Ai, B, Bi);                 /* A = top(0..3) */
    LOADSEG(4, B, Bi); LOADSEG(5, C, Ci);
    mergeTop16(B, Bi, C, Ci);                 /* B = top(4,5) */
    LOADSEG(6, C, Ci); LOADSEG(7, D, Di);
    mergeTop16(C, Ci, D, Di);                 /* C = top(6,7) */
    mergeTop16(B, Bi, C, Ci);                 /* B = top(4..7) */
    mergeTop16(A, Ai, B, Bi);                 /* A = top all  */

#pragma unroll
    for (int t = 0; t < 16; t++) g_knn[q*KNN + t] = Ai[t];
}

/* ====== K2: gather-mean -> fc1/GELU/LN1 -> fc2/GELU/LN2 -> dw -> pw (+BN stats) ====== */
#define K2_THREADS 256
#define RT         16
#define NTILES     (NROWS/RT)    /* 1024 */

/* pair-interleaved weight layouts: w[(k>>1)*256 + o*2 + (k&1)] */
#define OFF_W1   0
#define OFF_W2   (OFF_W1 + 64*128)
#define OFF_PWT  (OFF_W2 + 128*128)
#define OFF_X    (OFF_PWT + 128*128)
#define OFF_H    (OFF_X + RT*64)
#define OFF_H2   (OFF_H + RT*128)
#define SMEM_K2_FLOATS (OFF_H2 + RT*128)
#define SMEM_K2_BYTES  (SMEM_K2_FLOATS*4)    /* 184320 B */

__device__ __forceinline__ void ln_rows(float* buf, const float* __restrict__ g,
                                        const float* __restrict__ b,
                                        const float* __restrict__ sw,
                                        const float* __restrict__ sb, int tid)
{
    const int wid = tid >> 5, lane = tid & 31;
#pragma unroll
    for (int rr = 0; rr < 2; rr++){
        const int r = wid*2 + rr;
        float v0 = buf[r*128 +       lane];
        float v1 = buf[r*128 +  32 + lane];
        float v2 = buf[r*128 +  64 + lane];
        float v3 = buf[r*128 +  96 + lane];
        float s  = v0+v1+v2+v3;
        float s2 = v0*v0 + v1*v1 + v2*v2 + v3*v3;
#pragma unroll
        for (int o = 16; o > 0; o >>= 1){
            s  += __shfl_xor_sync(0xffffffffu, s,  o);
            s2 += __shfl_xor_sync(0xffffffffu, s2, o);
        }
        const float mu   = s  * (1.0f/128.0f);
        const float var  = s2 * (1.0f/128.0f) - mu*mu;
        const float rstd = rsqrtf(var + EPSF);
#pragma unroll
        for (int qq = 0; qq < 4; qq++){
            const int c = qq*32 + lane;
            float v  = (qq==0)?v0:(qq==1)?v1:(qq==2)?v2:v3;
            float nv = (v - mu)*rstd*g[c] + b[c];
            if (sw) nv = nv*sw[c] + sb[c];
            buf[r*128 + c] = nv;
        }
    }
}

extern __shared__ float smem[];

/* packed GEMM step over a k-chunk of 4 for 8 rows of one thread */
#define GEMM8_PACKED(wbase, xbase, rowstride, KDIM, ACC)              \
    for (int k = 0; k < (KDIM); k += 4){                              \
        const ull w01 = lds64((wbase) + (((k>>1)  )*256 + (o<<1))*4); \
        const ull w23 = lds64((wbase) + (((k>>1)+1)*256 + (o<<1))*4); \
        _Pragma("unroll")                                             \
        for (int r = 0; r < 8; r++){                                  \
            ull x01, x23;                                             \
            lds128p((xbase) + ((rh*8+r)*(rowstride) + k)*4, x01, x23);\
            ACC[r] = fma2(x01, w01, ACC[r]);                          \
            ACC[r] = fma2(x23, w23, ACC[r]);                          \
        }                                                             \
    }

__global__ void __launch_bounds__(K2_THREADS)
mlp_kernel(const float* __restrict__ feats,
           const float* __restrict__ fc1_w, const float* __restrict__ fc1_b,
           const float* __restrict__ ln1_g, const float* __restrict__ ln1_b,
           const float* __restrict__ fc2_w, const float* __restrict__ fc2_b,
           const float* __restrict__ ln2_g, const float* __restrict__ ln2_b,
           const float* __restrict__ dw_w,  const float* __restrict__ dw_b,
           const float* __restrict__ pw_w,  const float* __restrict__ pw_b)
{
    float* sx   = smem + OFF_X;
    float* sh   = smem + OFF_H;
    float* sh2  = smem + OFF_H2;

    const int tid = threadIdx.x;
    /* pair-interleaved weight staging */
    for (int i = tid; i < 64*128; i += K2_THREADS){
        int k = i >> 7, o2 = i & 127;
        smem[OFF_W1 + ((k>>1)<<8) + (o2<<1) + (k&1)] = fc1_w[i];
    }
    for (int i = tid; i < 128*128; i += K2_THREADS){
        int k = i >> 7, o2 = i & 127;
        smem[OFF_W2 + ((k>>1)<<8) + (o2<<1) + (k&1)] = fc2_w[i];
    }
    for (int i = tid; i < 128*128; i += K2_THREADS){
        int o2 = i >> 7, k = i & 127;            /* i = o*128 + k */
        smem[OFF_PWT + ((k>>1)<<8) + (o2<<1) + (k&1)] = pw_w[i];
    }

    const unsigned sb    = (unsigned)__cvta_generic_to_shared(smem);
    const unsigned w1b   = sb + OFF_W1*4;
    const unsigned w2b   = sb + OFF_W2*4;
    const unsigned pwb   = sb + OFF_PWT*4;
    const unsigned xb    = sb + OFF_X*4;
    const unsigned hb    = sb + OFF_H*4;
    const unsigned h2b   = sb + OFF_H2*4;

    const int o  = tid & 127;
    const int rh = tid >> 7;
    const float bias1 = fc1_b[o], bias2 = fc2_b[o], biasp = pw_b[o];
    float bn_s = 0.f, bn_q = 0.f;
    __syncthreads();

    for (int tile = blockIdx.x; tile < NTILES; tile += gridDim.x){
        /* ---- gather + mean over 16 neighbors ---- */
        {
            const int r  = tid >> 4, cg = tid & 15;
            const int row = tile*RT + r;
            float4 a = make_float4(0.f,0.f,0.f,0.f);
            const int* kp = &g_knn[row*KNN];
#pragma unroll
            for (int n = 0; n < KNN; n++){
                const int gi = kp[n];
                const float4 f = *reinterpret_cast<const float4*>(&feats[gi*IC + cg*4]);
                a.x += f.x; a.y += f.y; a.z += f.z; a.w += f.w;
            }
            const float inv = 1.0f/16.0f;
            *reinterpret_cast<float4*>(&sx[r*IC + cg*4]) =
                make_float4(a.x*inv, a.y*inv, a.z*inv, a.w*inv);
        }
        __syncthreads();

        /* ---- fc1 + GELU ---- */
        {
            ull acc[8];
#pragma unroll
            for (int r = 0; r < 8; r++) acc[r] = pk(bias1, 0.f);
            GEMM8_PACKED(w1b, xb, IC, IC, acc);
#pragma unroll
            for (int r = 0; r < 8; r++){
                float lo, hi; upk(acc[r], lo, hi);
                sh[(rh*8+r)*128 + o] = gelu_f(lo + hi);
            }
        }
        __syncthreads();
        ln_rows(sh, ln1_g, ln1_b, (const float*)0, (const float*)0, tid);
        __syncthreads();

        /* ---- fc2 + GELU ---- */
        {
            ull acc[8];
#pragma unroll
            for (int r = 0; r < 8; r++) acc[r] = pk(bias2, 0.f);
            GEMM8_PACKED(w2b, hb, 128, 128, acc);
#pragma unroll
            for (int r = 0; r < 8; r++){
                float lo, hi; upk(acc[r], lo, hi);
                sh2[(rh*8+r)*128 + o] = gelu_f(lo + hi);
            }
        }
        __syncthreads();
        ln_rows(sh2, ln2_g, ln2_b, dw_w, dw_b, tid);
        __syncthreads();

        /* ---- pointwise conv -> ypre (+ BN stats) ---- */
        {
            ull acc[8];
#pragma unroll
            for (int r = 0; r < 8; r++) acc[r] = pk(biasp, 0.f);
            GEMM8_PACKED(pwb, h2b, 128, 128, acc);
#pragma unroll
            for (int r = 0; r < 8; r++){
                float lo, hi; upk(acc[r], lo, hi);
                const float v = lo + hi;
                g_ypre[(tile*RT + rh*8 + r)*128 + o] = v;
                bn_s += v;
                bn_q  = fmaf(v, v, bn_q);
            }
        }
        __syncthreads();
    }

    /* ---- per-block BN partials (deterministic) ---- */
    sh [rh*128 + o] = bn_s;
    sh2[rh*128 + o] = bn_q;
    __syncthreads();
    if (tid < 128){
        g_part[(blockIdx.x*128 + tid)*2 + 0] = sh [tid] + sh [128 + tid];
        g_part[(blockIdx.x*128 + tid)*2 + 1] = sh2[tid] + sh2[128 + tid];
    }
}

/* ========== K4: BN finalize (inline) + BN apply + GELU + residual ========== */
#define K4_THREADS 256
__global__ void __launch_bounds__(K4_THREADS)
out_kernel(const float* __restrict__ feats,
           const float* __restrict__ proj_w, const float* __restrict__ proj_b,
           const float* __restrict__ bn_g,   const float* __restrict__ bn_b,
           float* __restrict__ out)
{
    __shared__ __align__(16) float sprojp[64*128];
    __shared__ __align__(16) float sfeat[RT*64];
    __shared__ float sred[256];
    __shared__ float smu[128], srs[128];

    const int tid = threadIdx.x;
    for (int i = tid; i < 64*128; i += K4_THREADS){
        int k = i >> 7, o2 = i & 127;
        sprojp[((k>>1)<<8) + (o2<<1) + (k&1)] = proj_w[i];
    }

    /* inline BN-stat finalize: every block computes identical mu/rstd */
    {
        const int c = tid & 127, which = tid >> 7;
        float acc = 0.f;
#pragma unroll 4
        for (int b = 0; b < K2_GRID; b++)
            acc += g_part[(b*128 + c)*2 + which];
        sred[tid] = acc;
        __syncthreads();
        if (tid < 128){
            const float mu  = sred[tid] * (1.0f/(float)NROWS);
            const float var = sred[128 + tid] * (1.0f/(float)NROWS) - mu*mu;
            smu[tid] = mu;
            srs[tid] = rsqrtf(var + EPSF);
        }
        __syncthreads();
    }

    const unsigned pb_ = (unsigned)__cvta_generic_to_shared(sprojp);
    const unsigned fb_ = (unsigned)__cvta_generic_to_shared(sfeat);
    const int o  = tid & 127;
    const int rh = tid >> 7;
    const float pb = proj_b[o];
    const float mu = smu[o], rs = srs[o];
    const float bg = bn_g[o], bb = bn_b[o];

    for (int tile = blockIdx.x; tile < NTILES; tile += gridDim.x){
        __syncthreads();
        for (int i = tid; i < RT*64; i += K4_THREADS)
            sfeat[i] = feats[tile*RT*64 + i];
        __syncthreads();

        ull acc[8];
#pragma unroll
        for (int r = 0; r < 8; r++) acc[r] = pk(pb, 0.f);
        GEMM8_PACKED(pb_, fb_, 64, 64, acc);

#pragma unroll
        for (int r = 0; r < 8; r++){
            const int row = tile*RT + rh*8 + r;
            float lo, hi; upk(acc[r], lo, hi);
            const float yv = g_ypre[row*128 + o];
            const float yn = (yv - mu)*rs*bg + bb;
            out[row*128 + o] = gelu_f(yn) + (lo + hi);
        }
    }
}

/* ============================ launcher ============================ */
extern "C" void kernel_launch(void* const* d_in, const int* in_sizes, int n_in,
                              void* d_out, int out_size)
{
    const float* pts    = (const float*)d_in[0];
    const float* feats  = (const float*)d_in[1];
    const float* fc1_w  = (const float*)d_in[2];
    const float* fc1_b  = (const float*)d_in[3];
    const float* ln1_g  = (const float*)d_in[4];
    const float* ln1_b  = (const float*)d_in[5];
    const float* fc2_w  = (const float*)d_in[6];
    const float* fc2_b  = (const float*)d_in[7];
    const float* ln2_g  = (const float*)d_in[8];
    const float* ln2_b  = (const float*)d_in[9];
    const float* dw_w   = (const float*)d_in[10];
    const float* dw_b   = (const float*)d_in[11];
    const float* pw_w   = (const float*)d_in[12];
    const float* pw_b   = (const float*)d_in[13];
    const float* bn_g   = (const float*)d_in[14];
    const float* bn_b   = (const float*)d_in[15];
    const float* proj_w = (const float*)d_in[16];
    const float* proj_b = (const float*)d_in[17];
    float* out = (float*)d_out;

    cudaFuncSetAttribute(mlp_kernel, cudaFuncAttributeMaxDynamicSharedMemorySize,
                         SMEM_K2_BYTES);

    dim3 g1(NROWS / K1_THREADS, GSEG);
    knn_seg_kernel<<<g1, K1_THREADS>>>(pts);
    knn_merge_kernel<<<NROWS/256, 256>>>();
    mlp_kernel<<<K2_GRID, K2_THREADS, SMEM_K2_BYTES>>>(feats,
        fc1_w, fc1_b, ln1_g, ln1_b, fc2_w, fc2_b, ln2_g, ln2_b,
        dw_w, dw_b, pw_w, pw_b);
    out_kernel<<<148, K4_THREADS>>>(feats, proj_w, proj_b, bn_g, bn_b, out);
}

// round 9
// speedup vs baseline: 1.0535x; 1.0535x over previous
#include <cuda_runtime.h>
#include <math.h>

#define BATCH 2
#define NPTS  8192
#define IC    64
#define OC    128
#define KNN   16
#define NROWS (BATCH*NPTS)      /* 16384 */
#define EPSF  1e-5f

#define GSEG  8                 /* KNN candidate segments per query */
#define SEGN  (NPTS/GSEG)       /* 1024 */
#define BCAP  40
#define BTRIG 32
#define K2_GRID 148

typedef unsigned long long ull;

/* ---------------- scratch (no allocations allowed) ---------------- */
__device__ int   g_knn[NROWS*KNN];
__device__ float g_ypre[NROWS*OC];
__device__ float g_segd[GSEG*KNN*NROWS];
__device__ int   g_segi[GSEG*KNN*NROWS];
__device__ float g_part[K2_GRID*OC*2];

__device__ __forceinline__ float gelu_f(float x){
    return 0.5f*x*(1.0f + erff(x*0.70710678118654752440f));
}

/* ---------------- packed f32x2 helpers (PURE asm: schedulable) ---------------- */
__device__ __forceinline__ ull pk(float lo, float hi){
    ull r; asm("mov.b64 %0,{%1,%2};" : "=l"(r) : "f"(lo), "f"(hi)); return r;
}
__device__ __forceinline__ void upk(ull v, float& lo, float& hi){
    asm("mov.b64 {%0,%1},%2;" : "=f"(lo), "=f"(hi) : "l"(v));
}
__device__ __forceinline__ ull mul2(ull a, ull b){
    ull r; asm("mul.rn.f32x2 %0,%1,%2;" : "=l"(r) : "l"(a), "l"(b)); return r;
}
__device__ __forceinline__ ull add2(ull a, ull b){
    ull r; asm("add.rn.f32x2 %0,%1,%2;" : "=l"(r) : "l"(a), "l"(b)); return r;
}
__device__ __forceinline__ ull fma2(ull a, ull b, ull c){
    ull r; asm("fma.rn.f32x2 %0,%1,%2,%3;" : "=l"(r) : "l"(a), "l"(b), "l"(c)); return r;
}

/* =============== K1a: segmented KNN, SoA tile + packed distances =============== */
#define K1_THREADS 128
#define TILE_C     SEGN

#define FLUSH() do{                                                   \
    for (int t = 0; t < cnt; t++){                                    \
        float d2f = bd[t]; int jj = bi[t];                            \
        _Pragma("unroll")                                             \
        for (int s = 0; s < KNN; s++){                                \
            bool  lt = d2f < kd[s];                                   \
            float od = kd[s]; int oi = ki[s];                         \
            kd[s] = lt ? d2f : od;  ki[s] = lt ? jj : oi;             \
            d2f   = lt ? od  : d2f; jj    = lt ? oi : jj;             \
        }                                                             \
    }                                                                 \
    cnt = 0; kmax = kd[KNN-1];                                        \
}while(0)

__global__ void __launch_bounds__(K1_THREADS)
knn_seg_kernel(const float* __restrict__ pts)
{
    __shared__ __align__(16) float sXx[TILE_C];
    __shared__ __align__(16) float sYy[TILE_C];
    __shared__ __align__(16) float sZz[TILE_C];
    __shared__ __align__(16) float sWw[TILE_C];

    const int q     = blockIdx.x * K1_THREADS + threadIdx.x;
    const int seg   = blockIdx.y;
    const int cbase = (q >> 13) << 13;
    const int sbase = cbase + seg*SEGN;

    const float qx = pts[q*3+0], qy = pts[q*3+1], qz = pts[q*3+2];
    const float qs = qx*qx + qy*qy + qz*qz;

    for (int t = threadIdx.x; t < TILE_C; t += K1_THREADS){
        const int j = sbase + t;
        float x = pts[j*3+0], y = pts[j*3+1], z = pts[j*3+2];
        sXx[t] = x; sYy[t] = y; sZz[t] = z;
        sWw[t] = x*x + y*y + z*z;
    }
    __syncthreads();

    const ull* pX = reinterpret_cast<const ull*>(sXx);
    const ull* pY = reinterpret_cast<const ull*>(sYy);
    const ull* pZ = reinterpret_cast<const ull*>(sZz);
    const ull* pW = reinterpret_cast<const ull*>(sWw);

    const ull qx2 = pk(qx,qx), qy2 = pk(qy,qy), qz2 = pk(qz,qz);
    const ull qs2 = pk(qs,qs), m2  = pk(-2.0f,-2.0f);

    float kd[KNN]; int ki[KNN];
#pragma unroll
    for (int s = 0; s < KNN; s++){ kd[s] = 3.4e38f; ki[s] = cbase; }
    float bd[BCAP]; int bi[BCAP];
    int   cnt = 0;
    float kmax = 3.4e38f;

#pragma unroll 2
    for (int p = 0; p < TILE_C/2; p++){
        const ull cx = pX[p];
        const ull cy = pY[p];
        const ull cz = pZ[p];
        const ull cw = pW[p];
        /* same per-element op order as scalar version: mul, fma, fma */
        ull dot  = fma2(qz2, cz, fma2(qy2, cy, mul2(qx2, cx)));
        ull base = add2(qs2, cw);
        ull d2p  = fma2(m2, dot, base);
        float d0, d1; upk(d2p, d0, d1);
        if (d0 < kmax){ bd[cnt] = d0; bi[cnt] = sbase + 2*p;     cnt++; }
        if (d1 < kmax){ bd[cnt] = d1; bi[cnt] = sbase + 2*p + 1; cnt++; }
        if (p & 1){
            if (__any_sync(0xffffffffu, cnt >= BTRIG)) FLUSH();
        }
    }
    FLUSH();

#pragma unroll
    for (int t = 0; t < KNN; t++){
        g_segd[(seg*KNN + t)*NROWS + q] = kd[t];
        g_segi[(seg*KNN + t)*NROWS + q] = ki[t];
    }
}

/* =============== K1b: bitonic top-16 merge tree (register-only) =============== */
__device__ __forceinline__ bool lexlt(float d1, int i1, float d2, int i2){
    return (d1 < d2) || (d1 == d2 && i1 < i2);
}

__device__ __forceinline__ void mergeTop16(float* ad, int* ai,
                                           const float* bdv, const int* biv)
{
    float td[16]; int ti[16];
#pragma unroll
    for (int i = 0; i < 16; i++){
        float db = bdv[15-i]; int ib = biv[15-i];
        bool t = lexlt(db, ib, ad[i], ai[i]);
        td[i] = t ? db : ad[i];
        ti[i] = t ? ib : ai[i];
    }
#pragma unroll
    for (int k = 8; k >= 1; k >>= 1){
#pragma unroll
        for (int i = 0; i < 16; i++){
            if ((i & k) == 0){
                const int j = i + k;
                bool sw = lexlt(td[j], ti[j], td[i], ti[i]);
                float d0 = td[i]; int i0 = ti[i];
                td[i] = sw ? td[j] : d0;   ti[i] = sw ? ti[j] : i0;
                td[j] = sw ? d0 : td[j];   ti[j] = sw ? i0 : ti[j];
            }
        }
    }
#pragma unroll
    for (int i = 0; i < 16; i++){ ad[i] = td[i]; ai[i] = ti[i]; }
}

#define LOADSEG(s, D, I) do{                                  \
    _Pragma("unroll")                                         \
    for (int t = 0; t < 16; t++){                             \
        D[t] = g_segd[((s)*KNN + t)*NROWS + q];               \
        I[t] = g_segi[((s)*KNN + t)*NROWS + q];               \
    }                                                         \
}while(0)

__global__ void __launch_bounds__(256)
knn_merge_kernel(void)
{
    const int q = blockIdx.x*256 + threadIdx.x;
    float A[16], B[16], C[16], D[16];
    int   Ai[16], Bi[16], Ci[16], Di[16];

    LOADSEG(0, A, Ai); LOADSEG(1, B, Bi);
    mergeTop16(A, Ai, B, Bi);
    LOADSEG(2, B, Bi); LOADSEG(3, C, Ci);
    mergeTop16(B, Bi, C, Ci);
    mergeTop16(A, Ai, B, Bi);
    LOADSEG(4, B, Bi); LOADSEG(5, C, Ci);
    mergeTop16(B, Bi, C, Ci);
    LOADSEG(6, C, Ci); LOADSEG(7, D, Di);
    mergeTop16(C, Ci, D, Di);
    mergeTop16(B, Bi, C, Ci);
    mergeTop16(A, Ai, B, Bi);

#pragma unroll
    for (int t = 0; t < 16; t++) g_knn[q*KNN + t] = Ai[t];
}

/* ====== K2: gather-mean -> fc1/GELU/LN1 -> fc2/GELU/LN2 -> dw -> pw (+BN stats) ====== */
#define K2_THREADS 512
#define RT         16
#define NTILES     (NROWS/RT)    /* 1024 */

/* pair-interleaved weight layouts: float idx (k>>1)*256 + o*2 + (k&1)  ==  ull idx (k>>1)*128 + o */
#define OFF_W1   0
#define OFF_W2   (OFF_W1 + 64*128)
#define OFF_PWT  (OFF_W2 + 128*128)
#define OFF_X    (OFF_PWT + 128*128)
#define OFF_H    (OFF_X + RT*64)
#define OFF_H2   (OFF_H + RT*128)
#define SMEM_K2_FLOATS (OFF_H2 + RT*128)
#define SMEM_K2_BYTES  (SMEM_K2_FLOATS*4)    /* 184320 B */

/* 16 warps, each warp handles one row of 128 channels */
__device__ __forceinline__ void ln_rows16(float* buf, const float* __restrict__ g,
                                          const float* __restrict__ b,
                                          const float* __restrict__ sw,
                                          const float* __restrict__ sb, int tid)
{
    const int r = tid >> 5, lane = tid & 31;
    float v0 = buf[r*128 +       lane];
    float v1 = buf[r*128 +  32 + lane];
    float v2 = buf[r*128 +  64 + lane];
    float v3 = buf[r*128 +  96 + lane];
    float s  = v0+v1+v2+v3;
    float s2 = v0*v0 + v1*v1 + v2*v2 + v3*v3;
#pragma unroll
    for (int o = 16; o > 0; o >>= 1){
        s  += __shfl_xor_sync(0xffffffffu, s,  o);
        s2 += __shfl_xor_sync(0xffffffffu, s2, o);
    }
    const float mu   = s  * (1.0f/128.0f);
    const float var  = s2 * (1.0f/128.0f) - mu*mu;
    const float rstd = rsqrtf(var + EPSF);
#pragma unroll
    for (int qq = 0; qq < 4; qq++){
        const int c = qq*32 + lane;
        float v  = (qq==0)?v0:(qq==1)?v1:(qq==2)?v2:v3;
        float nv = (v - mu)*rstd*g[c] + b[c];
        if (sw) nv = nv*sw[c] + sb[c];
        buf[r*128 + c] = nv;
    }
}

extern __shared__ float smem[];

/* packed GEMM over k for NR rows of one thread; WP: const ull* pair-interleaved,
   XP: const float* activations (rowstride mult of 4) */
#define GEMM_PACKED(WP, XP, rowstride, KDIM, NR, ACC)                          \
    _Pragma("unroll")                                                          \
    for (int k = 0; k < (KDIM); k += 4){                                       \
        const ull w01 = (WP)[((k>>1)  )*128 + o];                              \
        const ull w23 = (WP)[((k>>1)+1)*128 + o];                              \
        _Pragma("unroll")                                                      \
        for (int r = 0; r < (NR); r++){                                        \
            const ulonglong2 x = *reinterpret_cast<const ulonglong2*>(         \
                &(XP)[(rh*(NR)+r)*(rowstride) + k]);                           \
            ACC[r] = fma2(x.x, w01, ACC[r]);                                   \
            ACC[r] = fma2(x.y, w23, ACC[r]);                                   \
        }                                                                      \
    }

__global__ void __launch_bounds__(K2_THREADS)
mlp_kernel(const float* __restrict__ feats,
           const float* __restrict__ fc1_w, const float* __restrict__ fc1_b,
           const float* __restrict__ ln1_g, const float* __restrict__ ln1_b,
           const float* __restrict__ fc2_w, const float* __restrict__ fc2_b,
           const float* __restrict__ ln2_g, const float* __restrict__ ln2_b,
           const float* __restrict__ dw_w,  const float* __restrict__ dw_b,
           const float* __restrict__ pw_w,  const float* __restrict__ pw_b)
{
    float* sx   = smem + OFF_X;
    float* sh   = smem + OFF_H;
    float* sh2  = smem + OFF_H2;

    const int tid = threadIdx.x;
    for (int i = tid; i < 64*128; i += K2_THREADS){
        int k = i >> 7, o2 = i & 127;
        smem[OFF_W1 + ((k>>1)<<8) + (o2<<1) + (k&1)] = fc1_w[i];
    }
    for (int i = tid; i < 128*128; i += K2_THREADS){
        int k = i >> 7, o2 = i & 127;
        smem[OFF_W2 + ((k>>1)<<8) + (o2<<1) + (k&1)] = fc2_w[i];
    }
    for (int i = tid; i < 128*128; i += K2_THREADS){
        int o2 = i >> 7, k = i & 127;            /* i = o*128 + k */
        smem[OFF_PWT + ((k>>1)<<8) + (o2<<1) + (k&1)] = pw_w[i];
    }

    const ull* w1p = reinterpret_cast<const ull*>(smem + OFF_W1);
    const ull* w2p = reinterpret_cast<const ull*>(smem + OFF_W2);
    const ull* pwp = reinterpret_cast<const ull*>(smem + OFF_PWT);

    const int o  = tid & 127;
    const int rh = tid >> 7;                     /* 0..3, 4 rows each */
    const float bias1 = fc1_b[o], bias2 = fc2_b[o], biasp = pw_b[o];
    float bn_s = 0.f, bn_q = 0.f;
    __syncthreads();

    for (int tile = blockIdx.x; tile < NTILES; tile += gridDim.x){
        /* ---- gather + mean over 16 neighbors (first 256 threads) ---- */
        if (tid < 256){
            const int r  = tid >> 4, cg = tid & 15;
            const int row = tile*RT + r;
            float4 a = make_float4(0.f,0.f,0.f,0.f);
            const int* kp = &g_knn[row*KNN];
#pragma unroll
            for (int n = 0; n < KNN; n++){
                const int gi = kp[n];
                const float4 f = *reinterpret_cast<const float4*>(&feats[gi*IC + cg*4]);
                a.x += f.x; a.y += f.y; a.z += f.z; a.w += f.w;
            }
            const float inv = 1.0f/16.0f;
            *reinterpret_cast<float4*>(&sx[r*IC + cg*4]) =
                make_float4(a.x*inv, a.y*inv, a.z*inv, a.w*inv);
        }
        __syncthreads();

        /* ---- fc1 + GELU ---- */
        {
            ull acc[4];
#pragma unroll
            for (int r = 0; r < 4; r++) acc[r] = pk(bias1, 0.f);
            GEMM_PACKED(w1p, sx, IC, IC, 4, acc);
#pragma unroll
            for (int r = 0; r < 4; r++){
                float lo, hi; upk(acc[r], lo, hi);
                sh[(rh*4+r)*128 + o] = gelu_f(lo + hi);
            }
        }
        __syncthreads();
        ln_rows16(sh, ln1_g, ln1_b, (const float*)0, (const float*)0, tid);
        __syncthreads();

        /* ---- fc2 + GELU ---- */
        {
            ull acc[4];
#pragma unroll
            for (int r = 0; r < 4; r++) acc[r] = pk(bias2, 0.f);
            GEMM_PACKED(w2p, sh, 128, 128, 4, acc);
#pragma unroll
            for (int r = 0; r < 4; r++){
                float lo, hi; upk(acc[r], lo, hi);
                sh2[(rh*4+r)*128 + o] = gelu_f(lo + hi);
            }
        }
        __syncthreads();
        ln_rows16(sh2, ln2_g, ln2_b, dw_w, dw_b, tid);
        __syncthreads();

        /* ---- pointwise conv -> ypre (+ BN stats) ---- */
        {
            ull acc[4];
#pragma unroll
            for (int r = 0; r < 4; r++) acc[r] = pk(biasp, 0.f);
            GEMM_PACKED(pwp, sh2, 128, 128, 4, acc);
#pragma unroll
            for (int r = 0; r < 4; r++){
                float lo, hi; upk(acc[r], lo, hi);
                const float v = lo + hi;
                g_ypre[(tile*RT + rh*4 + r)*128 + o] = v;
                bn_s += v;
                bn_q  = fmaf(v, v, bn_q);
            }
        }
        __syncthreads();
    }

    /* ---- per-block BN partials (deterministic) ---- */
    sh[tid] = bn_s;
    sh2[tid] = bn_q;
    __syncthreads();
    if (tid < 128){
        g_part[(blockIdx.x*128 + tid)*2 + 0] =
            sh[tid] + sh[128+tid] + sh[256+tid] + sh[384+tid];
        g_part[(blockIdx.x*128 + tid)*2 + 1] =
            sh2[tid] + sh2[128+tid] + sh2[256+tid] + sh2[384+tid];
    }
}

/* ========== K4: BN finalize (inline) + BN apply + GELU + residual ========== */
#define K4_THREADS 256
#define K4_GRID    296
__global__ void __launch_bounds__(K4_THREADS)
out_kernel(const float* __restrict__ feats,
           const float* __restrict__ proj_w, const float* __restrict__ proj_b,
           const float* __restrict__ bn_g,   const float* __restrict__ bn_b,
           float* __restrict__ out)
{
    __shared__ __align__(16) float sprojp[64*128];
    __shared__ __align__(16) float sfeat[RT*64];
    __shared__ float sred[256];
    __shared__ float smu[128], srs[128];

    const int tid = threadIdx.x;
    for (int i = tid; i < 64*128; i += K4_THREADS){
        int k = i >> 7, o2 = i & 127;
        sprojp[((k>>1)<<8) + (o2<<1) + (k&1)] = proj_w[i];
    }

    /* inline BN-stat finalize: every block computes identical mu/rstd */
    {
        const int c = tid & 127, which = tid >> 7;
        float acc = 0.f;
#pragma unroll 4
        for (int b = 0; b < K2_GRID; b++)
            acc += g_part[(b*128 + c)*2 + which];
        sred[tid] = acc;
        __syncthreads();
        if (tid < 128){
            const float mu  = sred[tid] * (1.0f/(float)NROWS);
            const float var = sred[128 + tid] * (1.0f/(float)NROWS) - mu*mu;
            smu[tid] = mu;
            srs[tid] = rsqrtf(var + EPSF);
        }
        __syncthreads();
    }

    const ull* pjp = reinterpret_cast<const ull*>(sprojp);
    const int o  = tid & 127;
    const int rh = tid >> 7;                  /* 0..1, 8 rows each */
    const float pb = proj_b[o];
    const float mu = smu[o], rs = srs[o];
    const float bg = bn_g[o], bb = bn_b[o];

    for (int tile = blockIdx.x; tile < NTILES; tile += gridDim.x){
        __syncthreads();
        for (int i = tid; i < RT*64; i += K4_THREADS)
            sfeat[i] = feats[tile*RT*64 + i];
        __syncthreads();

        ull acc[8];
#pragma unroll
        for (int r = 0; r < 8; r++) acc[r] = pk(pb, 0.f);
        GEMM_PACKED(pjp, sfeat, 64, 64, 8, acc);

#pragma unroll
        for (int r = 0; r < 8; r++){
            const int row = tile*RT + rh*8 + r;
            float lo, hi; upk(acc[r], lo, hi);
            const float yv = g_ypre[row*128 + o];
            const float yn = (yv - mu)*rs*bg + bb;
            out[row*128 + o] = gelu_f(yn) + (lo + hi);
        }
    }
}

/* ============================ launcher ============================ */
extern "C" void kernel_launch(void* const* d_in, const int* in_sizes, int n_in,
                              void* d_out, int out_size)
{
    const float* pts    = (const float*)d_in[0];
    const float* feats  = (const float*)d_in[1];
    const float* fc1_w  = (const float*)d_in[2];
    const float* fc1_b  = (const float*)d_in[3];
    const float* ln1_g  = (const float*)d_in[4];
    const float* ln1_b  = (const float*)d_in[5];
    const float* fc2_w  = (const float*)d_in[6];
    const float* fc2_b  = (const float*)d_in[7];
    const float* ln2_g  = (const float*)d_in[8];
    const float* ln2_b  = (const float*)d_in[9];
    const float* dw_w   = (const float*)d_in[10];
    const float* dw_b   = (const float*)d_in[11];
    const float* pw_w   = (const float*)d_in[12];
    const float* pw_b   = (const float*)d_in[13];
    const float* bn_g   = (const float*)d_in[14];
    const float* bn_b   = (const float*)d_in[15];
    const float* proj_w = (const float*)d_in[16];
    const float* proj_b = (const float*)d_in[17];
    float* out = (float*)d_out;

    cudaFuncSetAttribute(mlp_kernel, cudaFuncAttributeMaxDynamicSharedMemorySize,
                         SMEM_K2_BYTES);

    dim3 g1(NROWS / K1_THREADS, GSEG);
    knn_seg_kernel<<<g1, K1_THREADS>>>(pts);
    knn_merge_kernel<<<NROWS/256, 256>>>();
    mlp_kernel<<<K2_GRID, K2_THREADS, SMEM_K2_BYTES>>>(feats,
        fc1_w, fc1_b, ln1_g, ln1_b, fc2_w, fc2_b, ln2_g, ln2_b,
        dw_w, dw_b, pw_w, pw_b);
    out_kernel<<<K4_GRID, K4_THREADS>>>(feats, proj_w, proj_b, bn_g, bn_b, out);
}

// round 11
// speedup vs baseline: 1.0743x; 1.0198x over previous
#include <cuda_runtime.h>
#include <math.h>

#define BATCH 2
#define NPTS  8192
#define IC    64
#define OC    128
#define KNN   16
#define NROWS (BATCH*NPTS)      /* 16384 */
#define EPSF  1e-5f

#define GSEG  8                 /* KNN candidate segments per query */
#define SEGN  (NPTS/GSEG)       /* 1024 */
#define BCAP  40
#define BTRIG 32
#define K2_GRID 148

typedef unsigned long long ull;

/* ---------------- scratch (no allocations allowed) ---------------- */
__device__ int   g_knn[NROWS*KNN];
__device__ float g_ypre[NROWS*OC];
__device__ float g_resid[NROWS*OC];
__device__ float g_segd[GSEG*KNN*NROWS];
__device__ int   g_segi[GSEG*KNN*NROWS];
__device__ float g_part[K2_GRID*OC*2];
__device__ float g_mu[OC];
__device__ float g_rstd[OC];

__device__ __forceinline__ float gelu_f(float x){
    return 0.5f*x*(1.0f + erff(x*0.70710678118654752440f));
}

/* ---------------- packed f32x2 helpers (PURE asm: schedulable) ---------------- */
__device__ __forceinline__ ull pk(float lo, float hi){
    ull r; asm("mov.b64 %0,{%1,%2};" : "=l"(r) : "f"(lo), "f"(hi)); return r;
}
__device__ __forceinline__ void upk(ull v, float& lo, float& hi){
    asm("mov.b64 {%0,%1},%2;" : "=f"(lo), "=f"(hi) : "l"(v));
}
__device__ __forceinline__ ull mul2(ull a, ull b){
    ull r; asm("mul.rn.f32x2 %0,%1,%2;" : "=l"(r) : "l"(a), "l"(b)); return r;
}
__device__ __forceinline__ ull add2(ull a, ull b){
    ull r; asm("add.rn.f32x2 %0,%1,%2;" : "=l"(r) : "l"(a), "l"(b)); return r;
}
__device__ __forceinline__ ull fma2(ull a, ull b, ull c){
    ull r; asm("fma.rn.f32x2 %0,%1,%2,%3;" : "=l"(r) : "l"(a), "l"(b), "l"(c)); return r;
}

/* =============== K1a: segmented KNN, SoA tile + packed distances =============== */
#define K1_THREADS 128
#define TILE_C     SEGN

#define FLUSH() do{                                                   \
    for (int t = 0; t < cnt; t++){                                    \
        float d2f = bd[t]; int jj = bi[t];                            \
        _Pragma("unroll")                                             \
        for (int s = 0; s < KNN; s++){                                \
            bool  lt = d2f < kd[s];                                   \
            float od = kd[s]; int oi = ki[s];                         \
            kd[s] = lt ? d2f : od;  ki[s] = lt ? jj : oi;             \
            d2f   = lt ? od  : d2f; jj    = lt ? oi : jj;             \
        }                                                             \
    }                                                                 \
    cnt = 0; kmax = kd[KNN-1];                                        \
}while(0)

__global__ void __launch_bounds__(K1_THREADS)
knn_seg_kernel(const float* __restrict__ pts)
{
    __shared__ __align__(16) float sXx[TILE_C];
    __shared__ __align__(16) float sYy[TILE_C];
    __shared__ __align__(16) float sZz[TILE_C];
    __shared__ __align__(16) float sWw[TILE_C];

    const int q     = blockIdx.x * K1_THREADS + threadIdx.x;
    const int seg   = blockIdx.y;
    const int cbase = (q >> 13) << 13;
    const int sbase = cbase + seg*SEGN;

    const float qx = pts[q*3+0], qy = pts[q*3+1], qz = pts[q*3+2];
    const float qs = qx*qx + qy*qy + qz*qz;

    for (int t = threadIdx.x; t < TILE_C; t += K1_THREADS){
        const int j = sbase + t;
        float x = pts[j*3+0], y = pts[j*3+1], z = pts[j*3+2];
        sXx[t] = x; sYy[t] = y; sZz[t] = z;
        sWw[t] = x*x + y*y + z*z;
    }
    __syncthreads();

    const ull* pX = reinterpret_cast<const ull*>(sXx);
    const ull* pY = reinterpret_cast<const ull*>(sYy);
    const ull* pZ = reinterpret_cast<const ull*>(sZz);
    const ull* pW = reinterpret_cast<const ull*>(sWw);

    const ull qx2 = pk(qx,qx), qy2 = pk(qy,qy), qz2 = pk(qz,qz);
    const ull qs2 = pk(qs,qs), m2  = pk(-2.0f,-2.0f);

    float kd[KNN]; int ki[KNN];
#pragma unroll
    for (int s = 0; s < KNN; s++){ kd[s] = 3.4e38f; ki[s] = cbase; }
    float bd[BCAP]; int bi[BCAP];
    int   cnt = 0;
    float kmax = 3.4e38f;

#pragma unroll 2
    for (int p = 0; p < TILE_C/2; p++){
        const ull cx = pX[p];
        const ull cy = pY[p];
        const ull cz = pZ[p];
        const ull cw = pW[p];
        /* same per-element op order as scalar version: mul, fma, fma */
        ull dot  = fma2(qz2, cz, fma2(qy2, cy, mul2(qx2, cx)));
        ull base = add2(qs2, cw);
        ull d2p  = fma2(m2, dot, base);
        float d0, d1; upk(d2p, d0, d1);
        if (d0 < kmax){ bd[cnt] = d0; bi[cnt] = sbase + 2*p;     cnt++; }
        if (d1 < kmax){ bd[cnt] = d1; bi[cnt] = sbase + 2*p + 1; cnt++; }
        if (p & 1){
            if (__any_sync(0xffffffffu, cnt >= BTRIG)) FLUSH();
        }
    }
    FLUSH();

#pragma unroll
    for (int t = 0; t < KNN; t++){
        g_segd[(seg*KNN + t)*NROWS + q] = kd[t];
        g_segi[(seg*KNN + t)*NROWS + q] = ki[t];
    }
}

/* =============== K1b: bitonic top-16 merge tree (register-only) =============== */
__device__ __forceinline__ bool lexlt(float d1, int i1, float d2, int i2){
    return (d1 < d2) || (d1 == d2 && i1 < i2);
}

__device__ __forceinline__ void mergeTop16(float* ad, int* ai,
                                           const float* bdv, const int* biv)
{
    float td[16]; int ti[16];
#pragma unroll
    for (int i = 0; i < 16; i++){
        float db = bdv[15-i]; int ib = biv[15-i];
        bool t = lexlt(db, ib, ad[i], ai[i]);
        td[i] = t ? db : ad[i];
        ti[i] = t ? ib : ai[i];
    }
#pragma unroll
    for (int k = 8; k >= 1; k >>= 1){
#pragma unroll
        for (int i = 0; i < 16; i++){
            if ((i & k) == 0){
                const int j = i + k;
                bool sw = lexlt(td[j], ti[j], td[i], ti[i]);
                float d0 = td[i]; int i0 = ti[i];
                td[i] = sw ? td[j] : d0;   ti[i] = sw ? ti[j] : i0;
                td[j] = sw ? d0 : td[j];   ti[j] = sw ? i0 : ti[j];
            }
        }
    }
#pragma unroll
    for (int i = 0; i < 16; i++){ ad[i] = td[i]; ai[i] = ti[i]; }
}

#define LOADSEG(s, D, I) do{                                  \
    _Pragma("unroll")                                         \
    for (int t = 0; t < 16; t++){                             \
        D[t] = g_segd[((s)*KNN + t)*NROWS + q];               \
        I[t] = g_segi[((s)*KNN + t)*NROWS + q];               \
    }                                                         \
}while(0)

__global__ void __launch_bounds__(256)
knn_merge_kernel(void)
{
    const int q = blockIdx.x*256 + threadIdx.x;
    float A[16], B[16], C[16], D[16];
    int   Ai[16], Bi[16], Ci[16], Di[16];

    LOADSEG(0, A, Ai); LOADSEG(1, B, Bi);
    mergeTop16(A, Ai, B, Bi);
    LOADSEG(2, B, Bi); LOADSEG(3, C, Ci);
    mergeTop16(B, Bi, C, Ci);
    mergeTop16(A, Ai, B, Bi);
    LOADSEG(4, B, Bi); LOADSEG(5, C, Ci);
    mergeTop16(B, Bi, C, Ci);
    LOADSEG(6, C, Ci); LOADSEG(7, D, Di);
    mergeTop16(C, Ci, D, Di);
    mergeTop16(B, Bi, C, Ci);
    mergeTop16(A, Ai, B, Bi);

#pragma unroll
    for (int t = 0; t < 16; t++) g_knn[q*KNN + t] = Ai[t];
}

/* ====== K2: gather-mean -> fc1/GELU/LN1 -> fc2/GELU/LN2 -> dw -> pw (+proj, +BN stats) ====== */
#define K2_THREADS 512
#define RT         16
#define NTILES     (NROWS/RT)    /* 1024 */

/* pair-interleaved weight layouts: float idx (k>>1)*256 + o*2 + (k&1)  ==  ull idx (k>>1)*128 + o */
#define OFF_W1   0
#define OFF_W2   (OFF_W1 + 64*128)
#define OFF_PWT  (OFF_W2 + 128*128)
#define OFF_PRJ  (OFF_PWT + 128*128)
#define OFF_X    (OFF_PRJ + 64*128)
#define OFF_XR   (OFF_X + RT*64)
#define OFF_H    (OFF_XR + RT*64)
#define OFF_H2   (OFF_H + RT*128)
#define SMEM_K2_FLOATS (OFF_H2 + RT*128)
#define SMEM_K2_BYTES  (SMEM_K2_FLOATS*4)    /* 221184 B */

/* 16 warps, each warp handles one row of 128 channels */
__device__ __forceinline__ void ln_rows16(float* buf, const float* __restrict__ g,
                                          const float* __restrict__ b,
                                          const float* __restrict__ sw,
                                          const float* __restrict__ sb, int tid)
{
    const int r = tid >> 5, lane = tid & 31;
    float v0 = buf[r*128 +       lane];
    float v1 = buf[r*128 +  32 + lane];
    float v2 = buf[r*128 +  64 + lane];
    float v3 = buf[r*128 +  96 + lane];
    float s  = v0+v1+v2+v3;
    float s2 = v0*v0 + v1*v1 + v2*v2 + v3*v3;
#pragma unroll
    for (int o = 16; o > 0; o >>= 1){
        s  += __shfl_xor_sync(0xffffffffu, s,  o);
        s2 += __shfl_xor_sync(0xffffffffu, s2, o);
    }
    const float mu   = s  * (1.0f/128.0f);
    const float var  = s2 * (1.0f/128.0f) - mu*mu;
    const float rstd = rsqrtf(var + EPSF);
#pragma unroll
    for (int qq = 0; qq < 4; qq++){
        const int c = qq*32 + lane;
        float v  = (qq==0)?v0:(qq==1)?v1:(qq==2)?v2:v3;
        float nv = (v - mu)*rstd*g[c] + b[c];
        if (sw) nv = nv*sw[c] + sb[c];
        buf[r*128 + c] = nv;
    }
}

extern __shared__ float smem[];

/* packed GEMM over k for NR rows of one thread; WP: const ull* pair-interleaved,
   XP: const float* activations (rowstride mult of 4) */
#define GEMM_PACKED(WP, XP, rowstride, KDIM, NR, ACC)                          \
    _Pragma("unroll")                                                          \
    for (int k = 0; k < (KDIM); k += 4){                                       \
        const ull w01 = (WP)[((k>>1)  )*128 + o];                              \
        const ull w23 = (WP)[((k>>1)+1)*128 + o];                              \
        _Pragma("unroll")                                                      \
        for (int r = 0; r < (NR); r++){                                        \
            const ulonglong2 x = *reinterpret_cast<const ulonglong2*>(         \
                &(XP)[(rh*(NR)+r)*(rowstride) + k]);                           \
            ACC[r] = fma2(x.x, w01, ACC[r]);                                   \
            ACC[r] = fma2(x.y, w23, ACC[r]);                                   \
        }                                                                      \
    }

__global__ void __launch_bounds__(K2_THREADS)
mlp_kernel(const float* __restrict__ feats,
           const float* __restrict__ fc1_w, const float* __restrict__ fc1_b,
           const float* __restrict__ ln1_g, const float* __restrict__ ln1_b,
           const float* __restrict__ fc2_w, const float* __restrict__ fc2_b,
           const float* __restrict__ ln2_g, const float* __restrict__ ln2_b,
           const float* __restrict__ dw_w,  const float* __restrict__ dw_b,
           const float* __restrict__ pw_w,  const float* __restrict__ pw_b,
           const float* __restrict__ proj_w,const float* __restrict__ proj_b)
{
    float* sx   = smem + OFF_X;
    float* sxr  = smem + OFF_XR;
    float* sh   = smem + OFF_H;
    float* sh2  = smem + OFF_H2;

    const int tid = threadIdx.x;
    for (int i = tid; i < 64*128; i += K2_THREADS){
        int k = i >> 7, o2 = i & 127;
        smem[OFF_W1  + ((k>>1)<<8) + (o2<<1) + (k&1)] = fc1_w[i];
        smem[OFF_PRJ + ((k>>1)<<8) + (o2<<1) + (k&1)] = proj_w[i];
    }
    for (int i = tid; i < 128*128; i += K2_THREADS){
        int k = i >> 7, o2 = i & 127;
        smem[OFF_W2 + ((k>>1)<<8) + (o2<<1) + (k&1)] = fc2_w[i];
    }
    for (int i = tid; i < 128*128; i += K2_THREADS){
        int o2 = i >> 7, k = i & 127;            /* i = o*128 + k */
        smem[OFF_PWT + ((k>>1)<<8) + (o2<<1) + (k&1)] = pw_w[i];
    }

    const ull* w1p = reinterpret_cast<const ull*>(smem + OFF_W1);
    const ull* w2p = reinterpret_cast<const ull*>(smem + OFF_W2);
    const ull* pwp = reinterpret_cast<const ull*>(smem + OFF_PWT);
    const ull* pjp = reinterpret_cast<const ull*>(smem + OFF_PRJ);

    const int o  = tid & 127;
    const int rh = tid >> 7;                     /* 0..3, 4 rows each */
    const float bias1 = fc1_b[o], bias2 = fc2_b[o], biasp = pw_b[o];
    const float biasj = proj_b[o];
    float bn_s = 0.f, bn_q = 0.f;
    __syncthreads();

    for (int tile = blockIdx.x; tile < NTILES; tile += gridDim.x){
        /* ---- gather + mean over 16 neighbors + raw feats rows (256 threads) ---- */
        if (tid < 256){
            const int r  = tid >> 4, cg = tid & 15;
            const int row = tile*RT + r;
            float4 a = make_float4(0.f,0.f,0.f,0.f);
            const int* kp = &g_knn[row*KNN];
#pragma unroll
            for (int n = 0; n < KNN; n++){
                const int gi = kp[n];
                const float4 f = *reinterpret_cast<const float4*>(&feats[gi*IC + cg*4]);
                a.x += f.x; a.y += f.y; a.z += f.z; a.w += f.w;
            }
            const float inv = 1.0f/16.0f;
            *reinterpret_cast<float4*>(&sx[r*IC + cg*4]) =
                make_float4(a.x*inv, a.y*inv, a.z*inv, a.w*inv);
        } else {
            const int t2 = tid - 256;
            const int r  = t2 >> 4, cg = t2 & 15;
            const int row = tile*RT + r;
            *reinterpret_cast<float4*>(&sxr[r*IC + cg*4]) =
                *reinterpret_cast<const float4*>(&feats[row*IC + cg*4]);
        }
        __syncthreads();

        /* ---- fc1 + GELU ---- */
        {
            ull acc[4];
#pragma unroll
            for (int r = 0; r < 4; r++) acc[r] = pk(bias1, 0.f);
            GEMM_PACKED(w1p, sx, IC, IC, 4, acc);
#pragma unroll
            for (int r = 0; r < 4; r++){
                float lo, hi; upk(acc[r], lo, hi);
                sh[(rh*4+r)*128 + o] = gelu_f(lo + hi);
            }
        }

        /* ---- proj residual (independent of fc1 result; no sync needed) ---- */
        {
            ull acc[4];
#pragma unroll
            for (int r = 0; r < 4; r++) acc[r] = pk(biasj, 0.f);
            GEMM_PACKED(pjp, sxr, IC, IC, 4, acc);
#pragma unroll
            for (int r = 0; r < 4; r++){
                float lo, hi; upk(acc[r], lo, hi);
                g_resid[(tile*RT + rh*4 + r)*128 + o] = lo + hi;
            }
        }
        __syncthreads();
        ln_rows16(sh, ln1_g, ln1_b, (const float*)0, (const float*)0, tid);
        __syncthreads();

        /* ---- fc2 + GELU ---- */
        {
            ull acc[4];
#pragma unroll
            for (int r = 0; r < 4; r++) acc[r] = pk(bias2, 0.f);
            GEMM_PACKED(w2p, sh, 128, 128, 4, acc);
#pragma unroll
            for (int r = 0; r < 4; r++){
                float lo, hi; upk(acc[r], lo, hi);
                sh2[(rh*4+r)*128 + o] = gelu_f(lo + hi);
            }
        }
        __syncthreads();
        ln_rows16(sh2, ln2_g, ln2_b, dw_w, dw_b, tid);
        __syncthreads();

        /* ---- pointwise conv -> ypre (+ BN stats) ---- */
        {
            ull acc[4];
#pragma unroll
            for (int r = 0; r < 4; r++) acc[r] = pk(biasp, 0.f);
            GEMM_PACKED(pwp, sh2, 128, 128, 4, acc);
#pragma unroll
            for (int r = 0; r < 4; r++){
                float lo, hi; upk(acc[r], lo, hi);
                const float v = lo + hi;
                g_ypre[(tile*RT + rh*4 + r)*128 + o] = v;
                bn_s += v;
                bn_q  = fmaf(v, v, bn_q);
            }
        }
        __syncthreads();
    }

    /* ---- per-block BN partials (deterministic) ---- */
    sh[tid] = bn_s;
    sh2[tid] = bn_q;
    __syncthreads();
    if (tid < 128){
        g_part[(blockIdx.x*128 + tid)*2 + 0] =
            sh[tid] + sh[128+tid] + sh[256+tid] + sh[384+tid];
        g_part[(blockIdx.x*128 + tid)*2 + 1] =
            sh2[tid] + sh2[128+tid] + sh2[256+tid] + sh2[384+tid];
    }
}

/* ================= K3: BN finalize — one block per channel ================= */
__global__ void __launch_bounds__(256) bnfinal_kernel(void)
{
    __shared__ float rs[256], rq[256];
    const int c = blockIdx.x, tid = threadIdx.x;
    float s = 0.f, s2 = 0.f;
    if (tid < K2_GRID){
        s  = g_part[(tid*128 + c)*2 + 0];
        s2 = g_part[(tid*128 + c)*2 + 1];
    }
    rs[tid] = s; rq[tid] = s2;
    __syncthreads();
#pragma unroll
    for (int off = 128; off > 0; off >>= 1){
        if (tid < off){ rs[tid] += rs[tid+off]; rq[tid] += rq[tid+off]; }
        __syncthreads();
    }
    if (tid == 0){
        const float mu  = rs[0] * (1.0f/(float)NROWS);
        const float var = rq[0] * (1.0f/(float)NROWS) - mu*mu;
        g_mu[c]   = mu;
        g_rstd[c] = rsqrtf(var + EPSF);
    }
}

/* ========== K4: element-wise BN apply + GELU + residual (pure stream) ========== */
#define K4_THREADS 256
#define K4_VEC     (NROWS*OC/4)     /* 524288 float4 groups */
__global__ void __launch_bounds__(K4_THREADS)
out_elem_kernel(const float* __restrict__ bn_g, const float* __restrict__ bn_b,
                float* __restrict__ out)
{
    const int i4 = blockIdx.x*K4_THREADS + threadIdx.x;   /* grid covers all */
    const int c0 = (i4*4) & 127;

    const float4 y = *reinterpret_cast<const float4*>(&g_ypre[i4*4]);
    const float4 rr = *reinterpret_cast<const float4*>(&g_resid[i4*4]);

    const float4 mu = *reinterpret_cast<const float4*>(&g_mu[c0]);
    const float4 rs = *reinterpret_cast<const float4*>(&g_rstd[c0]);
    const float4 gg = *reinterpret_cast<const float4*>(&bn_g[c0]);
    const float4 bb = *reinterpret_cast<const float4*>(&bn_b[c0]);

    float4 r;
    r.x = gelu_f((y.x - mu.x)*rs.x*gg.x + bb.x) + rr.x;
    r.y = gelu_f((y.y - mu.y)*rs.y*gg.y + bb.y) + rr.y;
    r.z = gelu_f((y.z - mu.z)*rs.z*gg.z + bb.z) + rr.z;
    r.w = gelu_f((y.w - mu.w)*rs.w*gg.w + bb.w) + rr.w;
    *reinterpret_cast<float4*>(&out[i4*4]) = r;
}

/* ============================ launcher ============================ */
extern "C" void kernel_launch(void* const* d_in, const int* in_sizes, int n_in,
                              void* d_out, int out_size)
{
    const float* pts    = (const float*)d_in[0];
    const float* feats  = (const float*)d_in[1];
    const float* fc1_w  = (const float*)d_in[2];
    const float* fc1_b  = (const float*)d_in[3];
    const float* ln1_g  = (const float*)d_in[4];
    const float* ln1_b  = (const float*)d_in[5];
    const float* fc2_w  = (const float*)d_in[6];
    const float* fc2_b  = (const float*)d_in[7];
    const float* ln2_g  = (const float*)d_in[8];
    const float* ln2_b  = (const float*)d_in[9];
    const float* dw_w   = (const float*)d_in[10];
    const float* dw_b   = (const float*)d_in[11];
    const float* pw_w   = (const float*)d_in[12];
    const float* pw_b   = (const float*)d_in[13];
    const float* bn_g   = (const float*)d_in[14];
    const float* bn_b   = (const float*)d_in[15];
    const float* proj_w = (const float*)d_in[16];
    const float* proj_b = (const float*)d_in[17];
    float* out = (float*)d_out;

    cudaFuncSetAttribute(mlp_kernel, cudaFuncAttributeMaxDynamicSharedMemorySize,
                         SMEM_K2_BYTES);

    dim3 g1(NROWS / K1_THREADS, GSEG);
    knn_seg_kernel<<<g1, K1_THREADS>>>(pts);
    knn_merge_kernel<<<NROWS/256, 256>>>();
    mlp_kernel<<<K2_GRID, K2_THREADS, SMEM_K2_BYTES>>>(feats,
        fc1_w, fc1_b, ln1_g, ln1_b, fc2_w, fc2_b, ln2_g, ln2_b,
        dw_w, dw_b, pw_w, pw_b, proj_w, proj_b);
    bnfinal_kernel<<<OC, 256>>>();
    out_elem_kernel<<<K4_VEC/K4_THREADS, K4_THREADS>>>(bn_g, bn_b, out);
}